// round 1
// baseline (speedup 1.0000x reference)
#include <cuda_runtime.h>
#include <math.h>

// Problem constants
#define S_LEN   2048
#define DMODEL  2048
#define NHEADS  16
#define DKH     128
#define BATCH   4
#define BHN     (BATCH * NHEADS)   // 64
#define E3      (3 * DMODEL)       // 6144
#define MROWS   (BATCH * S_LEN)    // 8192

// Scratch (static device globals: allocation-free rule)
__device__ float g_q[BHN * S_LEN * DKH];
__device__ float g_k[BHN * S_LEN * DKH];
__device__ float g_v[BHN * S_LEN * DKH];
__device__ float g_attn[BATCH * S_LEN * DMODEL];
__device__ float g_cos[S_LEN * (DKH / 2)];
__device__ float g_sin[S_LEN * (DKH / 2)];

// ---------------------------------------------------------------------------
// RoPE tables (fp64 for accuracy, tiny kernel)
// ---------------------------------------------------------------------------
__global__ void rope_tables_kernel() {
    int idx = blockIdx.x * blockDim.x + threadIdx.x;
    if (idx >= S_LEN * (DKH / 2)) return;
    int i = idx % (DKH / 2);
    int s = idx / (DKH / 2);
    double inv = exp(-((double)(2 * i) / (double)DKH) * log(10000.0));
    double ang = (double)s * inv;
    g_cos[idx] = (float)cos(ang);
    g_sin[idx] = (float)sin(ang);
}

// ---------------------------------------------------------------------------
// Apply RoPE in-place to g_q and g_k.  One thread per (bh, s, pair).
// ---------------------------------------------------------------------------
__global__ void rope_apply_kernel() {
    int idx = blockIdx.x * blockDim.x + threadIdx.x;  // < BHN*S_LEN*64
    int i  = idx & 63;
    int s  = (idx >> 6) & (S_LEN - 1);
    int bh = idx >> 17;
    if (bh >= BHN) return;
    float cs = g_cos[(s << 6) + i];
    float sn = g_sin[(s << 6) + i];
    size_t base = (((size_t)bh * S_LEN + s) << 7) + (i << 1);
    float2 q = *(float2*)&g_q[base];
    float2 k = *(float2*)&g_k[base];
    float2 qo = make_float2(q.x * cs - q.y * sn, q.x * sn + q.y * cs);
    float2 ko = make_float2(k.x * cs - k.y * sn, k.x * sn + k.y * cs);
    *(float2*)&g_q[base] = qo;
    *(float2*)&g_k[base] = ko;
}

// ---------------------------------------------------------------------------
// SGEMM  C[M,N] = A[M,K] * B[N,K]^T   (both K-major)
// Block tile 128x128, K-tile 8, 256 threads, 8x8 per thread.
// MODE 1: QKV — scatter output into g_q/g_k/g_v ([B,H,S,dk] layout)
// MODE 2: out-proj — A is g_attn (param A ignored), C written row-major
// ---------------------------------------------------------------------------
template <int MODE>
__global__ void __launch_bounds__(256, 2)
sgemm_nt(const float* __restrict__ A, const float* __restrict__ Bw,
         float* __restrict__ C, int M, int N, int K) {
    __shared__ float As[8 * 132];
    __shared__ float Bs[8 * 132];

    const int bm = blockIdx.y << 7;
    const int bn = blockIdx.x << 7;
    const int tid = threadIdx.x;
    const int tx = tid & 15, ty = tid >> 4;

    const float* Aarr = (MODE == 2) ? g_attn : A;
    const int lr = tid >> 1;            // row within 128-tile
    const int lk = (tid & 1) << 2;      // k offset 0 or 4
    const float* Ap = Aarr + (size_t)(bm + lr) * K + lk;
    const float* Bp = Bw + (size_t)(bn + lr) * K + lk;

    float acc[8][8];
#pragma unroll
    for (int i = 0; i < 8; i++)
#pragma unroll
        for (int j = 0; j < 8; j++) acc[i][j] = 0.0f;

    float4 af = *(const float4*)Ap;
    float4 bf = *(const float4*)Bp;

    for (int k0 = 0; k0 < K; k0 += 8) {
        __syncthreads();
        As[(lk + 0) * 132 + lr] = af.x;
        As[(lk + 1) * 132 + lr] = af.y;
        As[(lk + 2) * 132 + lr] = af.z;
        As[(lk + 3) * 132 + lr] = af.w;
        Bs[(lk + 0) * 132 + lr] = bf.x;
        Bs[(lk + 1) * 132 + lr] = bf.y;
        Bs[(lk + 2) * 132 + lr] = bf.z;
        Bs[(lk + 3) * 132 + lr] = bf.w;
        __syncthreads();
        if (k0 + 8 < K) {
            af = *(const float4*)(Ap + k0 + 8);
            bf = *(const float4*)(Bp + k0 + 8);
        }
#pragma unroll
        for (int kk = 0; kk < 8; kk++) {
            float a[8], b[8];
            *(float4*)(a)     = *(const float4*)&As[kk * 132 + (ty << 3)];
            *(float4*)(a + 4) = *(const float4*)&As[kk * 132 + (ty << 3) + 4];
            *(float4*)(b)     = *(const float4*)&Bs[kk * 132 + (tx << 3)];
            *(float4*)(b + 4) = *(const float4*)&Bs[kk * 132 + (tx << 3) + 4];
#pragma unroll
            for (int i = 0; i < 8; i++)
#pragma unroll
                for (int j = 0; j < 8; j++)
                    acc[i][j] = fmaf(a[i], b[j], acc[i][j]);
        }
    }

    if (MODE == 2) {
#pragma unroll
        for (int i = 0; i < 8; i++) {
            float* crow = C + (size_t)(bm + (ty << 3) + i) * N + bn + (tx << 3);
            *(float4*)(crow)     = make_float4(acc[i][0], acc[i][1], acc[i][2], acc[i][3]);
            *(float4*)(crow + 4) = make_float4(acc[i][4], acc[i][5], acc[i][6], acc[i][7]);
        }
    } else {
        // MODE 1: whole 128-wide n-tile shares (part, head)
        const int part = bn >> 11;
        const int h = (bn >> 7) & 15;
        const int dkbase = (bn & 127) + (tx << 3);
        float* dst = (part == 0) ? g_q : ((part == 1) ? g_k : g_v);
#pragma unroll
        for (int i = 0; i < 8; i++) {
            int m = bm + (ty << 3) + i;
            int b = m >> 11;
            int s = m & (S_LEN - 1);
            float* row = dst + (((size_t)(b * NHEADS + h) * S_LEN + s) << 7) + dkbase;
            *(float4*)(row)     = make_float4(acc[i][0], acc[i][1], acc[i][2], acc[i][3]);
            *(float4*)(row + 4) = make_float4(acc[i][4], acc[i][5], acc[i][6], acc[i][7]);
        }
    }
}

// ---------------------------------------------------------------------------
// Flash attention (causal, fp32).  Block = one (bh, q-tile of 64 rows).
// 256 threads as 16x16; smem Q/K/V tiles 64x128 (+pad) and P tile 64x64.
// ---------------------------------------------------------------------------
#define ATTN_SMEM_FLOATS (3 * 64 * 132 + 64 * 68)

__global__ void __launch_bounds__(256)
attn_kernel() {
    extern __shared__ float sm[];
    float* Qs = sm;
    float* Ks = sm + 64 * 132;
    float* Vs = sm + 2 * 64 * 132;
    float* Ps = sm + 3 * 64 * 132;

    const int qt = blockIdx.x;
    const int bh = blockIdx.y;
    const size_t base = (size_t)bh * S_LEN * DKH;
    const float* qp = g_q + base + ((size_t)qt << 6) * DKH;
    const float* kp = g_k + base;
    const float* vp = g_v + base;

    const int tid = threadIdx.x;
    const int tx = tid & 15, ty = tid >> 4;
    const int r0 = ty << 2;    // 4 score rows per thread
    const int c0 = tx << 2;    // 4 score cols per thread
    const int cv = tx << 3;    // 8 output cols per thread

    // load Q tile
    for (int i = tid; i < 64 * 32; i += 256) {
        int r = i >> 5, c4 = (i & 31) << 2;
        *(float4*)&Qs[r * 132 + c4] = *(const float4*)&qp[r * 128 + c4];
    }

    float o[4][8];
#pragma unroll
    for (int i = 0; i < 4; i++)
#pragma unroll
        for (int c = 0; c < 8; c++) o[i][c] = 0.0f;
    float mi[4] = {-INFINITY, -INFINITY, -INFINITY, -INFINITY};
    float li[4] = {0.0f, 0.0f, 0.0f, 0.0f};
    const float scale = 0.08838834764831845f;  // 1/sqrt(128)

    for (int j = 0; j <= qt; j++) {
        __syncthreads();  // previous O-gemm reads done (and Q load on iter 0)
        const float* kt = kp + ((size_t)j << 6) * DKH;
        const float* vt = vp + ((size_t)j << 6) * DKH;
        for (int i = tid; i < 64 * 32; i += 256) {
            int r = i >> 5, c4 = (i & 31) << 2;
            *(float4*)&Ks[r * 132 + c4] = *(const float4*)&kt[r * 128 + c4];
            *(float4*)&Vs[r * 132 + c4] = *(const float4*)&vt[r * 128 + c4];
        }
        __syncthreads();

        // S = Q * K^T (64x64, over dk=128)
        float s[4][4];
#pragma unroll
        for (int i = 0; i < 4; i++)
#pragma unroll
            for (int ii = 0; ii < 4; ii++) s[i][ii] = 0.0f;

#pragma unroll 4
        for (int k4 = 0; k4 < 32; k4++) {
            float q[4][4], kv[4][4];
#pragma unroll
            for (int i = 0; i < 4; i++)
                *(float4*)q[i] = *(const float4*)&Qs[(r0 + i) * 132 + (k4 << 2)];
#pragma unroll
            for (int ii = 0; ii < 4; ii++)
                *(float4*)kv[ii] = *(const float4*)&Ks[(c0 + ii) * 132 + (k4 << 2)];
#pragma unroll
            for (int i = 0; i < 4; i++)
#pragma unroll
                for (int ii = 0; ii < 4; ii++)
#pragma unroll
                    for (int t = 0; t < 4; t++)
                        s[i][ii] = fmaf(q[i][t], kv[ii][t], s[i][ii]);
        }

        // online softmax per row (rows owned across 16 tx lanes)
#pragma unroll
        for (int i = 0; i < 4; i++) {
            float sv[4];
#pragma unroll
            for (int ii = 0; ii < 4; ii++) {
                float v = s[i][ii] * scale;
                if (j == qt && (c0 + ii) > (r0 + i)) v = -1e30f;
                sv[ii] = v;
            }
            float rm = fmaxf(fmaxf(sv[0], sv[1]), fmaxf(sv[2], sv[3]));
#pragma unroll
            for (int off = 8; off >= 1; off >>= 1)
                rm = fmaxf(rm, __shfl_xor_sync(0xffffffffu, rm, off));
            float mn = fmaxf(mi[i], rm);
            float al = __expf(mi[i] - mn);
            float rs = 0.0f;
#pragma unroll
            for (int ii = 0; ii < 4; ii++) {
                float p = __expf(sv[ii] - mn);
                sv[ii] = p;
                rs += p;
            }
#pragma unroll
            for (int off = 8; off >= 1; off >>= 1)
                rs += __shfl_xor_sync(0xffffffffu, rs, off);
            li[i] = li[i] * al + rs;
            mi[i] = mn;
#pragma unroll
            for (int c = 0; c < 8; c++) o[i][c] *= al;
            *(float4*)&Ps[(r0 + i) * 68 + c0] = make_float4(sv[0], sv[1], sv[2], sv[3]);
        }
        __syncthreads();

        // O += P * V  (64x128, over 64)
#pragma unroll 4
        for (int jj4 = 0; jj4 < 16; jj4++) {
            float p[4][4];
#pragma unroll
            for (int i = 0; i < 4; i++)
                *(float4*)p[i] = *(const float4*)&Ps[(r0 + i) * 68 + (jj4 << 2)];
#pragma unroll
            for (int t = 0; t < 4; t++) {
                int jj = (jj4 << 2) + t;
                float v[8];
                *(float4*)(v)     = *(const float4*)&Vs[jj * 132 + cv];
                *(float4*)(v + 4) = *(const float4*)&Vs[jj * 132 + cv + 4];
#pragma unroll
                for (int i = 0; i < 4; i++)
#pragma unroll
                    for (int c = 0; c < 8; c++)
                        o[i][c] = fmaf(p[i][t], v[c], o[i][c]);
            }
        }
    }

    // epilogue: normalize and write to g_attn [B,S,D] with D = h*128+dk
    const int b = bh >> 4, h = bh & 15;
#pragma unroll
    for (int i = 0; i < 4; i++) {
        float inv = 1.0f / li[i];
        int srow = (qt << 6) + r0 + i;
        float* orow = g_attn + (((size_t)(b * S_LEN + srow)) << 11) + (h << 7) + cv;
        *(float4*)(orow)     = make_float4(o[i][0] * inv, o[i][1] * inv, o[i][2] * inv, o[i][3] * inv);
        *(float4*)(orow + 4) = make_float4(o[i][4] * inv, o[i][5] * inv, o[i][6] * inv, o[i][7] * inv);
    }
}

// ---------------------------------------------------------------------------
// kernel_launch
// ---------------------------------------------------------------------------
extern "C" void kernel_launch(void* const* d_in, const int* in_sizes, int n_in,
                              void* d_out, int out_size) {
    const float* x     = (const float*)d_in[0];
    const float* w_qkv = (const float*)d_in[1];
    const float* w_out = (const float*)d_in[2];
    float* out = (float*)d_out;

    cudaFuncSetAttribute(attn_kernel, cudaFuncAttributeMaxDynamicSharedMemorySize,
                         ATTN_SMEM_FLOATS * (int)sizeof(float));

    // RoPE tables (independent)
    rope_tables_kernel<<<(S_LEN * (DKH / 2) + 255) / 256, 256>>>();

    // QKV projection: [8192,6144] = x[8192,2048] * w_qkv[6144,2048]^T, scatter
    sgemm_nt<1><<<dim3(E3 / 128, MROWS / 128), 256>>>(x, w_qkv, nullptr,
                                                      MROWS, E3, DMODEL);

    // RoPE in place on q,k
    rope_apply_kernel<<<(BHN * S_LEN * 64) / 256, 256>>>();

    // causal flash attention
    attn_kernel<<<dim3(S_LEN / 64, BHN), 256,
                  ATTN_SMEM_FLOATS * (int)sizeof(float)>>>();

    // output projection: d_out[8192,2048] = g_attn * w_out^T
    sgemm_nt<2><<<dim3(DMODEL / 128, MROWS / 128), 256>>>(nullptr, w_out, out,
                                                          MROWS, DMODEL, DMODEL);
}